// round 16
// baseline (speedup 1.0000x reference)
#include <cuda_runtime.h>
#include <cstdint>

#define WD 128
#define HT 128
#define NB 8
#define NC 16
#define HW (HT*WD)
#define CHW (NC*HW)
#define HO 127
#define WO 127
#define TS 15            // output tile (15x15)
#define PS 16            // eval patch (16x16) = 256 units exactly
#define NBINS 512
#define NEDGE (NBINS+1)

__global__ void __launch_bounds__(256) kan_tile_kernel(
    const float* __restrict__ x,
    const float* __restrict__ base_weight,
    const float* __restrict__ spline_weight,
    const float* __restrict__ spline_scaler,
    const float* __restrict__ grid,
    float* __restrict__ out)
{
    // Power-basis coefficients per cell (build-phase only): 768 B
    __shared__ float4 staging[12 * 4];
    // Edge values of G_f(v) = silu(v)*bw_f + spline_f(v): 8.2 KB
    __shared__ float4 sedge[NEDGE];
    // Lerp table: per bin, 2 float4 = (G0,dG for taps 0,1),(taps 2,3): 16 KB
    __shared__ float4 tabVS[NBINS * 2];
    // Tap planes for the 16x16 patch: 4 KB
    __shared__ float sa0[PS][PS];
    __shared__ float sa1[PS][PS];
    __shared__ float sa2[PS][PS];
    __shared__ float sa3[PS][PS];

    const int tid = threadIdx.x;

    const float bw0 = __ldg(base_weight + 0);
    const float bw1 = __ldg(base_weight + 1);
    const float bw2 = __ldg(base_weight + 2);
    const float bw3 = __ldg(base_weight + 3);
    const float lo    = __ldg(grid + 0);
    const float hknot = __ldg(grid + 1) - lo;
    const float inv_h = 1.0f / hknot;
    const float span  = 11.0f * hknot;          // 11 cells of support
    const float binw  = span / (float)NBINS;
    const float inv_b = (float)NBINS / span;
    const float t0    = -lo * inv_b;

    // ── Build 1: power-basis coefficients (48 threads) ──
    if (tid < 12 * 4) {
        const int t = tid >> 2;
        const int k = tid & 3;
        float4 val = make_float4(0.f, 0.f, 0.f, 0.f);
        if (t <= 10) {
            float o[4];
#pragma unroll
            for (int f = 0; f < 4; f++) {
                const float sc = spline_scaler[f];
                float c[4];
#pragma unroll
                for (int jj = 0; jj < 4; jj++) {
                    const int idx = t - 3 + jj;
                    c[jj] = (idx >= 0 && idx < 8)
                          ? spline_weight[f * 8 + idx] * sc : 0.f;
                }
                float r;
                if (k == 0)      r = (c[0] + 4.f * c[1] + c[2]) * (1.f / 6.f);
                else if (k == 1) r = (c[2] - c[0]) * 0.5f;
                else if (k == 2) r = (c[0] - 2.f * c[1] + c[2]) * 0.5f;
                else             r = (3.f * (c[1] - c[2]) + c[3] - c[0]) * (1.f / 6.f);
                o[f] = r;
            }
            val = make_float4(o[0], o[1], o[2], o[3]);
        }
        staging[tid] = val;
    }
    __syncthreads();

    // ── Build 2: evaluate G at 513 edges ──
    for (int e = tid; e < NEDGE; e += 256) {
        const float ve = fmaf((float)e, binw, lo);
        const float pc = (ve - lo) * inv_h;
        int cell = (int)floorf(pc);
        cell = cell < 0 ? 0 : (cell > 10 ? 10 : cell);
        const float u = pc - (float)cell;

        const float4 A  = staging[cell * 4 + 0];
        const float4 Bc = staging[cell * 4 + 1];
        const float4 Cc = staging[cell * 4 + 2];
        const float4 Dc = staging[cell * 4 + 3];

        const float s = __fdividef(ve, 1.f + __expf(-ve));

        float4 g;
        g.x = fmaf(s, bw0, fmaf(fmaf(fmaf(Dc.x, u, Cc.x), u, Bc.x), u, A.x));
        g.y = fmaf(s, bw1, fmaf(fmaf(fmaf(Dc.y, u, Cc.y), u, Bc.y), u, A.y));
        g.z = fmaf(s, bw2, fmaf(fmaf(fmaf(Dc.z, u, Cc.z), u, Bc.z), u, A.z));
        g.w = fmaf(s, bw3, fmaf(fmaf(fmaf(Dc.w, u, Cc.w), u, Bc.w), u, A.w));
        sedge[e] = g;
    }
    __syncthreads();

    // ── Build 3: (value, slope) lerp table ──
    for (int i = tid; i < NBINS; i += 256) {
        const float4 g0 = sedge[i];
        const float4 g1 = sedge[i + 1];
        tabVS[i * 2 + 0] = make_float4(g0.x, g1.x - g0.x, g0.y, g1.y - g0.y);
        tabVS[i * 2 + 1] = make_float4(g0.z, g1.z - g0.z, g0.w, g1.w - g0.w);
    }
    __syncthreads();

    const int c0 = blockIdx.x * TS;
    const int r0 = blockIdx.y * TS;
    const int b  = blockIdx.z;

    const int rl = tid >> 4;
    const int cl = tid & 15;
    const int row = r0 + rl;
    const int col = c0 + cl;

    float a0 = 0.f, a1 = 0.f, a2 = 0.f, a3 = 0.f;

    if (row < HT && col < WD) {
        const float* xp = x + b * CHW + row * WD + col;
#pragma unroll
        for (int h = 0; h < 2; h++) {
            float v[8];
#pragma unroll
            for (int q = 0; q < 8; q++)            // front-batched: MLP=8
                v[q] = __ldg(xp + (h * 8 + q) * HW);

#pragma unroll
            for (int q = 0; q < 8; q++) {
                const float vv = v[q];
                const float t  = fmaf(vv, inv_b, t0);
                const float ft = floorf(t);
                const int   it = (int)ft;
                if ((unsigned)it < (unsigned)NBINS) {
                    const float frac = t - ft;
                    const float4 pA = tabVS[it * 2 + 0];
                    const float4 pB = tabVS[it * 2 + 1];
                    a0 += fmaf(pA.y, frac, pA.x);
                    a1 += fmaf(pA.w, frac, pA.z);
                    a2 += fmaf(pB.y, frac, pB.x);
                    a3 += fmaf(pB.w, frac, pB.z);
                } else {
                    // out of spline support: base path only (rare)
                    const float s = __fdividef(vv, 1.f + __expf(-vv));
                    a0 = fmaf(s, bw0, a0);
                    a1 = fmaf(s, bw1, a1);
                    a2 = fmaf(s, bw2, a2);
                    a3 = fmaf(s, bw3, a3);
                }
            }
        }
    }

    sa0[rl][cl] = a0;
    sa1[rl][cl] = a1;
    sa2[rl][cl] = a2;
    sa3[rl][cl] = a3;

    __syncthreads();

    // ── Combine + direct store (15x15 outputs) ──
    if (rl < TS && cl < TS) {
        const int r = r0 + rl;
        const int c = c0 + cl;
        if (r < HO && c < WO) {
            const float val = sa0[rl][cl]     + sa1[rl][cl + 1] +
                              sa2[rl + 1][cl] + sa3[rl + 1][cl + 1];
            out[(b * HO + r) * WO + c] = val;
        }
    }
}

extern "C" void kernel_launch(void* const* d_in, const int* in_sizes, int n_in,
                              void* d_out, int out_size)
{
    const float* x  = (const float*)d_in[0];
    const float* bw = (const float*)d_in[1];
    const float* sw = (const float*)d_in[2];
    const float* ss = (const float*)d_in[3];
    const float* gr = (const float*)d_in[4];
    float* out = (float*)d_out;

    (void)in_sizes; (void)n_in; (void)out_size;

    dim3 gs((WO + TS - 1) / TS, (HO + TS - 1) / TS, NB);   // 9 x 9 x 8 = 648
    kan_tile_kernel<<<gs, 256>>>(x, bw, sw, ss, gr, out);
}

// round 17
// speedup vs baseline: 1.4177x; 1.4177x over previous
#include <cuda_runtime.h>

#define WD 128
#define HT 128
#define NB 8
#define NC 16
#define HW (HT*WD)
#define CHW (NC*HW)
#define HO 127
#define WO 127
#define NBLOCKS 512

// 4 pre-shifted tap planes, SoA, 8 MB. Combine reads all 4 at the SAME index.
__device__ float g_Y[4][NB][HT][WD];
// Monotonic arrival counter (zero-init at load; never reset — generation math).
__device__ unsigned long long g_done;

__global__ void __launch_bounds__(256, 4) kan_persistent_kernel(
    const float* __restrict__ x,
    const float* __restrict__ base_weight,
    const float* __restrict__ spline_weight,
    const float* __restrict__ spline_scaler,
    const float* __restrict__ grid,
    float* __restrict__ out)
{
    // Per-lane-replicated scaled spline weight table (R1 layout, verbatim).
    // Row p <-> basis j = p-3 (zero outside [0,8)); rows 14..17 zero rows.
    __shared__ float4 tab[18 * 32];

    const int tid = threadIdx.x;
    for (int e = tid; e < 18 * 32; e += 256) {
        int p = e >> 5;
        int j = p - 3;
        float4 val = make_float4(0.f, 0.f, 0.f, 0.f);
        if (j >= 0 && j < 8) {
            val.x = spline_weight[0 * 8 + j] * spline_scaler[0];
            val.y = spline_weight[1 * 8 + j] * spline_scaler[1];
            val.z = spline_weight[2 * 8 + j] * spline_scaler[2];
            val.w = spline_weight[3 * 8 + j] * spline_scaler[3];
        }
        tab[e] = val;
    }
    __syncthreads();

    const float bw0 = __ldg(base_weight + 0);
    const float bw1 = __ldg(base_weight + 1);
    const float bw2 = __ldg(base_weight + 2);
    const float bw3 = __ldg(base_weight + 3);
    const float g0  = __ldg(grid + 0);
    const float invh = 1.0f / (__ldg(grid + 1) - g0);

    const int n = blockIdx.x * 256 + tid;
    const int j = n & (WD - 1);
    const int i = (n >> 7) & (HT - 1);
    const int b = n >> 14;
    const int lane = tid & 31;

    const float* xp = x + b * CHW + i * WD + j;

    float a0 = 0.f, a1 = 0.f, a2 = 0.f, a3 = 0.f;

#pragma unroll
    for (int c = 0; c < NC; c++) {
        const float v = __ldg(xp + c * HW);

        const float p = (v - g0) * invh;
        const float fc = floorf(p);
        const float u = p - fc;
        const int cell = (int)fc;
        const int cb = ((unsigned)cell <= 10u) ? cell : 14;

        const float u2 = u * u;
        const float u3 = u2 * u;
        const float w0 = fmaf(fmaf(fmaf(-(1.f / 6.f), u, 0.5f), u, -0.5f), u, 1.f / 6.f);
        const float w1 = fmaf(0.5f, u3, 2.f / 3.f) - u2;
        const float w2 = fmaf(-0.5f, u3, fmaf(0.5f, u2, fmaf(0.5f, u, 1.f / 6.f)));
        const float w3 = u3 * (1.f / 6.f);

        const float s = __fdividef(v, 1.f + __expf(-v));
        a0 = fmaf(s, bw0, a0);
        a1 = fmaf(s, bw1, a1);
        a2 = fmaf(s, bw2, a2);
        a3 = fmaf(s, bw3, a3);

        const float4* tp = tab + cb * 32 + lane;
        const float4 c0 = tp[0];
        const float4 c1 = tp[32];
        const float4 c2 = tp[64];
        const float4 c3 = tp[96];

        a0 = fmaf(w0, c0.x, a0); a1 = fmaf(w0, c0.y, a1);
        a2 = fmaf(w0, c0.z, a2); a3 = fmaf(w0, c0.w, a3);
        a0 = fmaf(w1, c1.x, a0); a1 = fmaf(w1, c1.y, a1);
        a2 = fmaf(w1, c1.z, a2); a3 = fmaf(w1, c1.w, a3);
        a0 = fmaf(w2, c2.x, a0); a1 = fmaf(w2, c2.y, a1);
        a2 = fmaf(w2, c2.z, a2); a3 = fmaf(w2, c2.w, a3);
        a0 = fmaf(w3, c3.x, a0); a1 = fmaf(w3, c3.y, a1);
        a2 = fmaf(w3, c3.z, a2); a3 = fmaf(w3, c3.w, a3);
    }

    // Pre-shifted stores: combine later reads all 4 planes at index (b,i,j).
    // Wrapped slots (row/col 127 of shifted planes) are never read.
    const int base = b * HW;
    const int jm = (j - 1) & (WD - 1);
    const int im = (i - 1) & (HT - 1);
    (&g_Y[0][0][0][0])[base + i  * WD + j ] = a0;
    (&g_Y[1][0][0][0])[base + i  * WD + jm] = a1;
    (&g_Y[2][0][0][0])[base + im * WD + j ] = a2;
    (&g_Y[3][0][0][0])[base + im * WD + jm] = a3;

    // ── Grid-wide barrier (all 512 blocks are co-resident: 512 <= 148*4) ──
    __syncthreads();                 // all stores of this block issued
    if (tid == 0) {
        __threadfence();             // publish stores before arrival
        const unsigned long long p = atomicAdd(&g_done, 1ULL);
        // Launch-start value is the largest multiple of NBLOCKS <= p.
        const unsigned long long target =
            (p / NBLOCKS) * NBLOCKS + NBLOCKS;
        const volatile unsigned long long* dp =
            (const volatile unsigned long long*)&g_done;
        while (*dp < target) { }
        __threadfence();             // acquire before reading peers' planes
    }
    __syncthreads();

    // ── Combine: each thread finishes its own pixel ──
    if (i < HO && j < WO) {
        const int m = base + i * WD + j;
        const float p0 = (&g_Y[0][0][0][0])[m];
        const float p1 = (&g_Y[1][0][0][0])[m];
        const float p2 = (&g_Y[2][0][0][0])[m];
        const float p3 = (&g_Y[3][0][0][0])[m];
        out[(b * HO + i) * WO + j] = (p0 + p1) + (p2 + p3);
    }
}

extern "C" void kernel_launch(void* const* d_in, const int* in_sizes, int n_in,
                              void* d_out, int out_size)
{
    const float* x  = (const float*)d_in[0];
    const float* bw = (const float*)d_in[1];
    const float* sw = (const float*)d_in[2];
    const float* ss = (const float*)d_in[3];
    const float* gr = (const float*)d_in[4];
    float* out = (float*)d_out;

    (void)in_sizes; (void)n_in; (void)out_size;

    kan_persistent_kernel<<<NBLOCKS, 256>>>(x, bw, sw, ss, gr, out);
}